// round 7
// baseline (speedup 1.0000x reference)
#include <cuda_runtime.h>
#include <math.h>

#define H 4096

// Scratch: mv outputs + intermediate vectors. __device__ global (no alloc).
__device__ float g_scratch[36 * H];

struct P {
    const float* L; const float* R;
    const float* x; const float* hp;
    const float* b; const float* Wsc;
    float* xL; float* hL; float* hR;          // hR: l=0..1 only
    float* Rr; float* Rz1;
    float* Rrh; float* RoneMZ; float* Rz2h;
    float* Lht; float* Lzh;
    float* r; float* z1; float* rh; float* oneMZ; float* z2h;
    float* htilde; float* zhtil;
    float* out;
};

// ---------------- helpers ----------------
__device__ __forceinline__ float4 f4add(float4 a, float4 b) {
    return make_float4(a.x + b.x, a.y + b.y, a.z + b.z, a.w + b.w);
}
__device__ __forceinline__ float4 f4fma(float4 a, float4 b, float4 c) {
    return make_float4(a.x * b.x + c.x, a.y * b.y + c.y, a.z * b.z + c.z, a.w * b.w + c.w);
}
__device__ __forceinline__ float4 f4smad(float s, float4 a, float4 acc) {
    return make_float4(s * a.x + acc.x, s * a.y + acc.y, s * a.z + acc.z, s * a.w + acc.w);
}
__device__ __forceinline__ float4 f4rsub1(float4 a) {
    return make_float4(1.f - a.x, 1.f - a.y, 1.f - a.z, 1.f - a.w);
}
__device__ __forceinline__ float ftanh(float x) { return 1.f - 2.f / (1.f + __expf(2.f * x)); }
__device__ __forceinline__ float fsig(float x)  { return 1.f / (1.f + __expf(-x)); }
__device__ __forceinline__ float4 f4tanh(float4 a) {
    return make_float4(ftanh(a.x), ftanh(a.y), ftanh(a.z), ftanh(a.w));
}
__device__ __forceinline__ float4 f4sig(float4 a) {
    return make_float4(fsig(a.x), fsig(a.y), fsig(a.z), fsig(a.w));
}
__device__ __forceinline__ float dot4(float4 a, float4 b) {
    return a.x * b.x + a.y * b.y + a.z * b.z + a.w * b.w;
}
__device__ __forceinline__ float4 ld4(const float* p, int i) {
    return __ldg(((const float4*)p) + i);
}
__device__ __forceinline__ float wred(float v) {
    v += __shfl_down_sync(0xffffffffu, v, 16);
    v += __shfl_down_sync(0xffffffffu, v, 8);
    v += __shfl_down_sync(0xffffffffu, v, 4);
    v += __shfl_down_sync(0xffffffffu, v, 2);
    v += __shfl_down_sync(0xffffffffu, v, 1);
    return v;
}

// Candidate values for the score_mix fused into stage MODE (2,3,4).
template<int MODE>
__device__ __forceinline__ void cands(const P& p, int idx, int l, float4* cc) {
    float4 b_ = ld4(p.b + l * H, idx);
    if (MODE == 2) {
        if (l < 3) {
            float4 hl = ld4(p.hL + l * H, idx);
            float4 rr = ld4(p.Rr + l * H, idx);
            float4 rz = ld4(p.Rz1 + l * H, idx);
            cc[0] = f4fma(hl, rr, b_);
            cc[1] = f4rsub1(f4add(rz, b_));
            cc[2] = f4fma(hl, rz, b_);
        } else {
            float4 hp4 = ld4(p.hp, idx);
            float4 r4  = ld4(p.r, idx);
            float4 z4  = ld4(p.z1, idx);
            cc[0] = f4fma(hp4, r4, b_);
            cc[1] = f4rsub1(f4add(z4, b_));
            cc[2] = f4fma(hp4, z4, b_);
        }
    } else if (MODE == 3) {
        if (l < 3)
            cc[0] = f4tanh(f4add(f4add(ld4(p.xL + l * H, idx), ld4(p.Rrh + l * H, idx)), b_));
        else
            cc[0] = f4tanh(f4add(f4add(ld4(p.x, idx), ld4(p.rh, idx)), b_));
    } else {  // MODE == 4
        if (l < 3)
            cc[0] = f4fma(ld4(p.Lht + l * H, idx), ld4(p.RoneMZ + l * H, idx), b_);
        else
            cc[0] = f4fma(ld4(p.htilde, idx), ld4(p.oneMZ, idx), b_);
    }
}

// ---------------------------------------------------------------------------
// Fused kernel: [prologue -> vsm] + streaming matvec, ONE 64-col tile/block.
// Block = 256 threads = 8 warps. Warp w handles rows [512w, 512w+512);
// lane owns 2 contiguous columns (float2) -> private accumulation, NO
// cross-lane reduction. Epilogue: one __syncthreads + 8-term fixed sum.
// All blocks co-resident (>=6 blocks/SM) -> barriers overlap with other
// blocks' streaming; no waves.
// MODE 0: A grid 320 (L x {x,hp} l=0..2 ; R x {hp} l=0..1)
// MODE 1: B grid 192 (sigmoid glue; R x {r,z1})
// MODE 2: C grid 192 (3-way score_mix; R x {rh,oneMZ,z2h})
// MODE 3: D grid 192 (h_tilde mix; L x {htilde})
// MODE 4: E grid 192 (zh_tilde mix; L x {zhtil})
// ---------------------------------------------------------------------------
template<int MODE>
__global__ void __launch_bounds__(256, (MODE == 2) ? 4 : 6) fused_kernel(P p) {
    extern __shared__ float vsm[];                 // [NVST][H] input vectors
    constexpr int NVST = (MODE == 2) ? 3 : ((MODE == 3 || MODE == 4) ? 1 : 2);
    __shared__ float part[NVST][8][64];            // per-warp partials
    __shared__ float red[12][8];
    __shared__ float wsm[3][4];

    const int t = threadIdx.x;                     // 0..255
    const int lane = t & 31, warp = t >> 5;
    const int bx = blockIdx.x;

    // ---------------- prologue: fill vsm ----------------
    if (MODE == 0) {
        #pragma unroll
        for (int c = 0; c < 4; ++c) {
            int idx = t + c * 256;
            ((float4*)vsm)[idx]       = ld4(p.x, idx);
            ((float4*)(vsm + H))[idx] = ld4(p.hp, idx);
        }
        __syncthreads();
    } else if (MODE == 1) {
        #pragma unroll
        for (int c = 0; c < 4; ++c) {
            int idx = t + c * 256;
            float4 z14 = f4sig(f4add(f4add(ld4(p.xL, idx),     ld4(p.hR, idx)),     ld4(p.b, idx)));
            float4 r4  = f4sig(f4add(f4add(ld4(p.xL + H, idx), ld4(p.hR + H, idx)), ld4(p.b + H, idx)));
            ((float4*)vsm)[idx]       = r4;    // v0 = r
            ((float4*)(vsm + H))[idx] = z14;   // v1 = z1
            if (bx == 0) {
                ((float4*)p.r)[idx]  = r4;
                ((float4*)p.z1)[idx] = z14;
            }
        }
        if (bx == 0 && t < 3) p.out[4096 + t] = (t == 1) ? 1.f : 0.f;
        __syncthreads();
    } else {
        constexpr int NM = (MODE == 2) ? 3 : 1;
        float s[NM * 4];
        #pragma unroll
        for (int d = 0; d < NM * 4; ++d) s[d] = 0.f;

        #pragma unroll
        for (int c = 0; c < 4; ++c) {
            int idx = t + c * 256;
            float4 ws = ld4(p.Wsc, idx);
            #pragma unroll
            for (int ll = 0; ll < 4; ++ll) {
                float4 cc[NM];
                cands<MODE>(p, idx, ll, cc);
                #pragma unroll
                for (int m = 0; m < NM; ++m) s[m * 4 + ll] += dot4(cc[m], ws);
            }
        }
        #pragma unroll
        for (int d = 0; d < NM * 4; ++d) {
            float v = wred(s[d]);
            if (lane == 0) red[d][warp] = v;
        }
        __syncthreads();
        if (t == 0) {
            #pragma unroll
            for (int m = 0; m < NM; ++m) {
                float sc[4];
                #pragma unroll
                for (int l2 = 0; l2 < 4; ++l2) {
                    float a = 0.f;
                    #pragma unroll
                    for (int w2 = 0; w2 < 8; ++w2) a += red[m * 4 + l2][w2];
                    sc[l2] = a;
                }
                int amax = 0; float m1 = sc[0];
                for (int l2 = 1; l2 < 4; ++l2) if (sc[l2] > m1) { m1 = sc[l2]; amax = l2; }
                float m2 = -INFINITY;
                for (int l2 = 0; l2 < 4; ++l2) if (l2 != amax && sc[l2] > m2) m2 = sc[l2];
                float e[4], se = 0.f;
                for (int l2 = 0; l2 < 4; ++l2) { e[l2] = __expf(sc[l2] - m1); se += e[l2]; }
                for (int l2 = 0; l2 < 4; ++l2) wsm[m][l2] = e[l2] / se;
                if (bx == 0) {
                    int slot = (MODE == 2) ? (m * 2) : ((MODE == 3) ? 1 : 3);
                    p.out[4096 + 3 + slot] = (float)amax;
                    p.out[4096 + 9 + slot] = m1 - m2;
                }
            }
        }
        __syncthreads();

        float* gv[NM];
        if (MODE == 2) { gv[0] = p.rh; gv[1] = p.oneMZ; gv[2] = p.z2h; }
        if (MODE == 3) { gv[0] = p.htilde; }
        if (MODE == 4) { gv[0] = p.zhtil; }
        #pragma unroll
        for (int c = 0; c < 4; ++c) {
            int idx = t + c * 256;
            float4 v[NM];
            #pragma unroll
            for (int m = 0; m < NM; ++m) v[m] = make_float4(0.f, 0.f, 0.f, 0.f);
            #pragma unroll
            for (int ll = 0; ll < 4; ++ll) {
                float4 cc[NM];
                cands<MODE>(p, idx, ll, cc);
                #pragma unroll
                for (int m = 0; m < NM; ++m) v[m] = f4smad(wsm[m][ll], cc[m], v[m]);
            }
            #pragma unroll
            for (int m = 0; m < NM; ++m) {
                ((float4*)(vsm + m * H))[idx] = v[m];
                if (bx == 0) ((float4*)gv[m])[idx] = v[m];
            }
        }
        __syncthreads();
    }

    // ---------------- streaming matvec: one 64-col tile ----------------
    int unit = bx >> 6;                 // 64 tiles per (W,l) unit
    const int c0 = (bx & 63) << 6;      // 64-col tile base
    int l, nv;
    const float* W;
    float *y0 = nullptr, *y1 = nullptr, *y2 = nullptr;
    const float *v0 = vsm, *v1 = vsm + H, *v2 = vsm + 2 * H;
    if (MODE == 0) {
        if (unit < 3) { W = p.L; l = unit;     nv = 2; y0 = p.xL; y1 = p.hL; }
        else          { W = p.R; l = unit - 3; nv = 1; y0 = p.hR; v0 = vsm + H; }
    } else {
        l = unit; nv = (MODE == 2) ? 3 : ((MODE == 1) ? 2 : 1);
        if (MODE == 1) { W = p.R; y0 = p.Rr;  y1 = p.Rz1; }
        if (MODE == 2) { W = p.R; y0 = p.Rrh; y1 = p.RoneMZ; y2 = p.Rz2h; }
        if (MODE == 3) { W = p.L; y0 = p.Lht; }
        if (MODE == 4) { W = p.L; y0 = p.Lzh; }
    }

    // warp handles rows [512*warp, 512*warp+512); lane owns cols c0+2*lane(+1)
    const float* __restrict__ Wb =
        W + (size_t)l * H * H + (size_t)(warp * 512) * H + c0 + 2 * lane;
    const float* vp0 = v0 + warp * 512;
    const float* vp1 = v1 + warp * 512;
    const float* vp2 = v2 + warp * 512;

    float2 a0 = make_float2(0.f, 0.f), a1 = a0, a2 = a0;

    if (NVST == 1 || nv == 1) {
        #pragma unroll 8
        for (int i = 0; i < 512; ++i) {
            float2 w = __ldg((const float2*)(Wb + (size_t)i * H));
            float v = vp0[i];
            a0.x += w.x * v; a0.y += w.y * v;
        }
    } else if (nv == 2) {
        #pragma unroll 8
        for (int i = 0; i < 512; ++i) {
            float2 w = __ldg((const float2*)(Wb + (size_t)i * H));
            float s0 = vp0[i], s1 = vp1[i];
            a0.x += w.x * s0; a0.y += w.y * s0;
            a1.x += w.x * s1; a1.y += w.y * s1;
        }
    } else {
        #pragma unroll 8
        for (int i = 0; i < 512; ++i) {
            float2 w = __ldg((const float2*)(Wb + (size_t)i * H));
            float s0 = vp0[i], s1 = vp1[i], s2 = vp2[i];
            a0.x += w.x * s0; a0.y += w.y * s0;
            a1.x += w.x * s1; a1.y += w.y * s1;
            a2.x += w.x * s2; a2.y += w.y * s2;
        }
    }

    part[0][warp][2 * lane] = a0.x; part[0][warp][2 * lane + 1] = a0.y;
    if (NVST > 1 && nv > 1) { part[1][warp][2 * lane] = a1.x; part[1][warp][2 * lane + 1] = a1.y; }
    if (NVST > 2 && nv > 2) { part[2][warp][2 * lane] = a2.x; part[2][warp][2 * lane + 1] = a2.y; }
    __syncthreads();

    // t < 64*nv: fixed-order 8-term sum, direct store
    if (t < 64 * nv) {
        const int m = t >> 6, c = t & 63;
        float acc = 0.f;
        #pragma unroll
        for (int w2 = 0; w2 < 8; ++w2) acc += part[m][w2][c];
        float* y = (m == 0) ? y0 : ((m == 1) ? y1 : y2);
        y[l * H + c0 + c] = acc;
    }
}

// ---------------------------------------------------------------------------
// Final score_mix: h_next = mix(Lzh + Rz2h + b), cand3 = zhtil + z2h + b3.
// ---------------------------------------------------------------------------
__global__ void __launch_bounds__(1024) final_kernel(P p) {
    const int t = threadIdx.x;
    const int lane = t & 31, warp = t >> 5;
    __shared__ float red2[4][32];
    __shared__ float wsh[4];

    float4 ws = ld4(p.Wsc, t);
    float4 cc[4];
    #pragma unroll
    for (int l = 0; l < 3; ++l)
        cc[l] = f4add(f4add(ld4(p.Lzh + l * H, t), ld4(p.Rz2h + l * H, t)), ld4(p.b + l * H, t));
    cc[3] = f4add(f4add(ld4(p.zhtil, t), ld4(p.z2h, t)), ld4(p.b + 3 * H, t));

    #pragma unroll
    for (int l = 0; l < 4; ++l) {
        float v = wred(dot4(cc[l], ws));
        if (lane == 0) red2[l][warp] = v;
    }
    __syncthreads();
    if (warp == 0) {
        float v[4];
        #pragma unroll
        for (int l = 0; l < 4; ++l) {
            v[l] = red2[l][lane];
            #pragma unroll
            for (int off = 16; off > 0; off >>= 1)
                v[l] += __shfl_down_sync(0xffffffffu, v[l], off);
        }
        if (lane == 0) {
            int amax = 0; float m1 = v[0];
            for (int l = 1; l < 4; ++l) if (v[l] > m1) { m1 = v[l]; amax = l; }
            float m2 = -INFINITY;
            for (int l = 0; l < 4; ++l) if (l != amax && v[l] > m2) m2 = v[l];
            float e[4], se = 0.f;
            for (int l = 0; l < 4; ++l) { e[l] = __expf(v[l] - m1); se += e[l]; }
            for (int l = 0; l < 4; ++l) wsh[l] = e[l] / se;
            p.out[4096 + 3 + 5] = (float)amax;
            p.out[4096 + 9 + 5] = m1 - m2;
        }
    }
    __syncthreads();

    float4 o = make_float4(0.f, 0.f, 0.f, 0.f);
    #pragma unroll
    for (int l = 0; l < 4; ++l) o = f4smad(wsh[l], cc[l], o);
    ((float4*)p.out)[t] = o;
}

// ---------------------------------------------------------------------------
// Launch sequence (graph-capturable: kernel launches only, default stream).
// ---------------------------------------------------------------------------
extern "C" void kernel_launch(void* const* d_in, const int* in_sizes, int n_in,
                              void* d_out_v, int out_size) {
    float* S = nullptr;
    cudaGetSymbolAddress((void**)&S, g_scratch);

    P p;
    p.L   = (const float*)d_in[2];
    p.R   = (const float*)d_in[3];
    p.x   = (const float*)d_in[0];
    p.hp  = (const float*)d_in[1];
    p.b   = (const float*)d_in[4];
    p.Wsc = (const float*)d_in[5];
    p.out = (float*)d_out_v;

    p.xL     = S + 0 * H;   p.hL     = S + 3 * H;   p.hR     = S + 6 * H;  // hR: 2H
    p.Rr     = S + 8 * H;   p.Rz1    = S + 11 * H;
    p.Rrh    = S + 14 * H;  p.RoneMZ = S + 17 * H;  p.Rz2h   = S + 20 * H;
    p.Lht    = S + 23 * H;  p.Lzh    = S + 26 * H;
    p.r      = S + 29 * H;  p.z1     = S + 30 * H;  p.rh     = S + 31 * H;
    p.oneMZ  = S + 32 * H;  p.z2h    = S + 33 * H;
    p.htilde = S + 34 * H;  p.zhtil  = S + 35 * H;

    const int DSM1 = 1 * H * (int)sizeof(float);   // 16KB
    const int DSM2 = 2 * H * (int)sizeof(float);   // 32KB
    const int DSM3 = 3 * H * (int)sizeof(float);   // 48KB
    cudaFuncSetAttribute(fused_kernel<0>, cudaFuncAttributeMaxDynamicSharedMemorySize, DSM2);
    cudaFuncSetAttribute(fused_kernel<1>, cudaFuncAttributeMaxDynamicSharedMemorySize, DSM2);
    cudaFuncSetAttribute(fused_kernel<2>, cudaFuncAttributeMaxDynamicSharedMemorySize, DSM3);
    cudaFuncSetAttribute(fused_kernel<3>, cudaFuncAttributeMaxDynamicSharedMemorySize, DSM1);
    cudaFuncSetAttribute(fused_kernel<4>, cudaFuncAttributeMaxDynamicSharedMemorySize, DSM1);

    fused_kernel<0><<<320, 256, DSM2>>>(p);  // A: L x {x,hp}, R x {hp}      320MB
    fused_kernel<1><<<192, 256, DSM2>>>(p);  // B: glue + R x {r,z1}         192MB
    fused_kernel<2><<<192, 256, DSM3>>>(p);  // C: 3-mix + R x {rh,oMZ,z2h}  192MB
    fused_kernel<3><<<192, 256, DSM1>>>(p);  // D: h_tilde + L x {htilde}    192MB
    fused_kernel<4><<<192, 256, DSM1>>>(p);  // E: zh_tilde + L x {zhtil}    192MB
    final_kernel<<<1, 1024>>>(p);            // F: h_next
}

// round 8
// speedup vs baseline: 1.6306x; 1.6306x over previous
#include <cuda_runtime.h>
#include <math.h>

#define H 4096

// Scratch: finals (36H) + row-partials (72H). __device__ global (no alloc).
__device__ float g_scratch[108 * H];
__device__ int g_ctr[8];      // work-steal counters, reset in final_kernel
__device__ int g_tick[320];   // per-(unit,colblock) completion tickets, self-reset

struct P {
    const float* L; const float* R;
    const float* x; const float* hp;
    const float* b; const float* Wsc;
    float* xL; float* hL; float* hR;          // hR: l=0..1 only
    float* Rr; float* Rz1;
    float* Rrh; float* RoneMZ; float* Rz2h;
    float* Lht; float* Lzh;
    float* r; float* z1; float* rh; float* oneMZ; float* z2h;
    float* htilde; float* zhtil;
    float* part;                               // [3 slots][8 rp][3*H]
    float* out;
};

// ---------------- helpers ----------------
__device__ __forceinline__ float4 f4add(float4 a, float4 b) {
    return make_float4(a.x + b.x, a.y + b.y, a.z + b.z, a.w + b.w);
}
__device__ __forceinline__ float4 f4fma(float4 a, float4 b, float4 c) {
    return make_float4(a.x * b.x + c.x, a.y * b.y + c.y, a.z * b.z + c.z, a.w * b.w + c.w);
}
__device__ __forceinline__ float4 f4smad(float s, float4 a, float4 acc) {
    return make_float4(s * a.x + acc.x, s * a.y + acc.y, s * a.z + acc.z, s * a.w + acc.w);
}
__device__ __forceinline__ float4 f4rsub1(float4 a) {
    return make_float4(1.f - a.x, 1.f - a.y, 1.f - a.z, 1.f - a.w);
}
__device__ __forceinline__ float ftanh(float x) { return 1.f - 2.f / (1.f + __expf(2.f * x)); }
__device__ __forceinline__ float fsig(float x)  { return 1.f / (1.f + __expf(-x)); }
__device__ __forceinline__ float4 f4tanh(float4 a) {
    return make_float4(ftanh(a.x), ftanh(a.y), ftanh(a.z), ftanh(a.w));
}
__device__ __forceinline__ float4 f4sig(float4 a) {
    return make_float4(fsig(a.x), fsig(a.y), fsig(a.z), fsig(a.w));
}
__device__ __forceinline__ float dot4(float4 a, float4 b) {
    return a.x * b.x + a.y * b.y + a.z * b.z + a.w * b.w;
}
__device__ __forceinline__ float4 ld4(const float* p, int i) {
    return __ldg(((const float4*)p) + i);
}
__device__ __forceinline__ float wred(float v) {
    v += __shfl_down_sync(0xffffffffu, v, 16);
    v += __shfl_down_sync(0xffffffffu, v, 8);
    v += __shfl_down_sync(0xffffffffu, v, 4);
    v += __shfl_down_sync(0xffffffffu, v, 2);
    v += __shfl_down_sync(0xffffffffu, v, 1);
    return v;
}

// Candidate values for the score_mix fused into stage MODE (2,3,4).
template<int MODE>
__device__ __forceinline__ void cands(const P& p, int idx, int l, float4* cc) {
    float4 b_ = ld4(p.b + l * H, idx);
    if (MODE == 2) {
        if (l < 3) {
            float4 hl = ld4(p.hL + l * H, idx);
            float4 rr = ld4(p.Rr + l * H, idx);
            float4 rz = ld4(p.Rz1 + l * H, idx);
            cc[0] = f4fma(hl, rr, b_);
            cc[1] = f4rsub1(f4add(rz, b_));
            cc[2] = f4fma(hl, rz, b_);
        } else {
            float4 hp4 = ld4(p.hp, idx);
            float4 r4  = ld4(p.r, idx);
            float4 z4  = ld4(p.z1, idx);
            cc[0] = f4fma(hp4, r4, b_);
            cc[1] = f4rsub1(f4add(z4, b_));
            cc[2] = f4fma(hp4, z4, b_);
        }
    } else if (MODE == 3) {
        if (l < 3)
            cc[0] = f4tanh(f4add(f4add(ld4(p.xL + l * H, idx), ld4(p.Rrh + l * H, idx)), b_));
        else
            cc[0] = f4tanh(f4add(f4add(ld4(p.x, idx), ld4(p.rh, idx)), b_));
    } else {  // MODE == 4
        if (l < 3)
            cc[0] = f4fma(ld4(p.Lht + l * H, idx), ld4(p.RoneMZ + l * H, idx), b_);
        else
            cc[0] = f4fma(ld4(p.htilde, idx), ld4(p.oneMZ, idx), b_);
    }
}

// ---------------------------------------------------------------------------
// Fused kernel: [prologue -> vsm] + work-stealing streaming matvec (R4
// geometry). Block (16,32)=512 thr, grid 296 (2 blocks/SM). Tile = 64 cols x
// 512 rows (128KB). Each tile writes a row-partial; the 8th finisher per
// (unit,colblock) (ticket atomic) sums 8 partials in fixed order -> final.
// MODE 0: A  NT=2560 (L x {x,hp} l=0..2 ; R x {hp} l=0..1)
// MODE 1: B  NT=1536 (sigmoid glue; R x {r,z1})
// MODE 2: C  NT=1536 (3-way score_mix; R x {rh,oneMZ,z2h})
// MODE 3: D  NT=1536 (h_tilde mix; L x {htilde})
// MODE 4: E  NT=1536 (zh_tilde mix; L x {zhtil})
// ---------------------------------------------------------------------------
template<int MODE>
__global__ void __launch_bounds__(512, 2) fused_kernel(P p) {
    extern __shared__ float vsm[];                 // [NVST][H] input vectors
    constexpr int NVST = (MODE == 2) ? 3 : ((MODE == 3 || MODE == 4) ? 1 : 2);
    constexpr int NT = (MODE == 0) ? 2560 : 1536;
    __shared__ float4 smred[NVST][32][16];
    __shared__ float red[12][16];
    __shared__ float wsm[3][4];
    __shared__ int stile, sold;

    const int tx = threadIdx.x, ty = threadIdx.y;  // 16 x 32
    const int t = ty * 16 + tx;
    const int lane = t & 31, warp = t >> 5;
    const int bx = blockIdx.x;

    // ---------------- prologue: fill vsm ----------------
    if (MODE == 0) {
        #pragma unroll
        for (int c = 0; c < 2; ++c) {
            int idx = t + c * 512;
            ((float4*)vsm)[idx]       = ld4(p.x, idx);
            ((float4*)(vsm + H))[idx] = ld4(p.hp, idx);
        }
        __syncthreads();
    } else if (MODE == 1) {
        #pragma unroll
        for (int c = 0; c < 2; ++c) {
            int idx = t + c * 512;
            float4 z14 = f4sig(f4add(f4add(ld4(p.xL, idx),     ld4(p.hR, idx)),     ld4(p.b, idx)));
            float4 r4  = f4sig(f4add(f4add(ld4(p.xL + H, idx), ld4(p.hR + H, idx)), ld4(p.b + H, idx)));
            ((float4*)vsm)[idx]       = r4;    // v0 = r
            ((float4*)(vsm + H))[idx] = z14;   // v1 = z1
            if (bx == 0) {
                ((float4*)p.r)[idx]  = r4;
                ((float4*)p.z1)[idx] = z14;
            }
        }
        if (bx == 0 && t < 3) p.out[4096 + t] = (t == 1) ? 1.f : 0.f;
        __syncthreads();
    } else {
        constexpr int NM = (MODE == 2) ? 3 : 1;
        float s[NM * 4];
        #pragma unroll
        for (int d = 0; d < NM * 4; ++d) s[d] = 0.f;

        #pragma unroll
        for (int c = 0; c < 2; ++c) {
            int idx = t + c * 512;
            float4 ws = ld4(p.Wsc, idx);
            #pragma unroll
            for (int ll = 0; ll < 4; ++ll) {
                float4 cc[NM];
                cands<MODE>(p, idx, ll, cc);
                #pragma unroll
                for (int m = 0; m < NM; ++m) s[m * 4 + ll] += dot4(cc[m], ws);
            }
        }
        #pragma unroll
        for (int d = 0; d < NM * 4; ++d) {
            float v = wred(s[d]);
            if (lane == 0) red[d][warp] = v;
        }
        __syncthreads();
        if (t == 0) {
            #pragma unroll
            for (int m = 0; m < NM; ++m) {
                float sc[4];
                #pragma unroll
                for (int l2 = 0; l2 < 4; ++l2) {
                    float a = 0.f;
                    #pragma unroll
                    for (int w2 = 0; w2 < 16; ++w2) a += red[m * 4 + l2][w2];
                    sc[l2] = a;
                }
                int amax = 0; float m1 = sc[0];
                for (int l2 = 1; l2 < 4; ++l2) if (sc[l2] > m1) { m1 = sc[l2]; amax = l2; }
                float m2 = -INFINITY;
                for (int l2 = 0; l2 < 4; ++l2) if (l2 != amax && sc[l2] > m2) m2 = sc[l2];
                float e[4], se = 0.f;
                for (int l2 = 0; l2 < 4; ++l2) { e[l2] = __expf(sc[l2] - m1); se += e[l2]; }
                for (int l2 = 0; l2 < 4; ++l2) wsm[m][l2] = e[l2] / se;
                if (bx == 0) {
                    int slot = (MODE == 2) ? (m * 2) : ((MODE == 3) ? 1 : 3);
                    p.out[4096 + 3 + slot] = (float)amax;
                    p.out[4096 + 9 + slot] = m1 - m2;
                }
            }
        }
        __syncthreads();

        float* gv[NM];
        if (MODE == 2) { gv[0] = p.rh; gv[1] = p.oneMZ; gv[2] = p.z2h; }
        if (MODE == 3) { gv[0] = p.htilde; }
        if (MODE == 4) { gv[0] = p.zhtil; }
        #pragma unroll
        for (int c = 0; c < 2; ++c) {
            int idx = t + c * 512;
            float4 v[NM];
            #pragma unroll
            for (int m = 0; m < NM; ++m) v[m] = make_float4(0.f, 0.f, 0.f, 0.f);
            #pragma unroll
            for (int ll = 0; ll < 4; ++ll) {
                float4 cc[NM];
                cands<MODE>(p, idx, ll, cc);
                #pragma unroll
                for (int m = 0; m < NM; ++m) v[m] = f4smad(wsm[m][ll], cc[m], v[m]);
            }
            #pragma unroll
            for (int m = 0; m < NM; ++m) {
                ((float4*)(vsm + m * H))[idx] = v[m];
                if (bx == 0) ((float4*)gv[m])[idx] = v[m];
            }
        }
        __syncthreads();
    }

    // ---------------- work-stealing streaming matvec ----------------
    for (;;) {
        if (t == 0) stile = atomicAdd(&g_ctr[MODE], 1);
        __syncthreads();
        const int tile = stile;
        __syncthreads();           // protect stile before next iteration's write
        if (tile >= NT) break;

        const int unit = tile >> 9;       // 512 tiles per (W,l) unit
        const int rem = tile & 511;
        const int kb = rem & 63;          // 64-col block
        const int rp = rem >> 6;          // row part 0..7 (512 rows each)

        int l, nv, mslot0;
        const float* W;
        float *y0 = nullptr, *y1 = nullptr, *y2 = nullptr;
        const float *v0 = vsm, *v1 = vsm + H, *v2 = vsm + 2 * H;
        if (MODE == 0) {
            if (unit < 3) { W = p.L; l = unit;     nv = 2; mslot0 = 0; y0 = p.xL; y1 = p.hL; }
            else          { W = p.R; l = unit - 3; nv = 1; mslot0 = 2; y0 = p.hR; v0 = vsm + H; }
        } else {
            l = unit; mslot0 = 0;
            nv = (MODE == 2) ? 3 : ((MODE == 1) ? 2 : 1);
            if (MODE == 1) { W = p.R; y0 = p.Rr;  y1 = p.Rz1; }
            if (MODE == 2) { W = p.R; y0 = p.Rrh; y1 = p.RoneMZ; y2 = p.Rz2h; }
            if (MODE == 3) { W = p.L; y0 = p.Lht; }
            if (MODE == 4) { W = p.L; y0 = p.Lzh; }
        }

        const int k0 = (kb << 6) + (tx << 2);
        const int h0 = rp * 512 + ty * 16;
        const float* __restrict__ Wp = W + (size_t)l * H * H + (size_t)h0 * H + k0;
        const float* v0s = v0 + h0;
        const float* v1s = v1 + h0;
        const float* v2s = v2 + h0;
        float4 a0 = make_float4(0.f, 0.f, 0.f, 0.f), a1 = a0, a2 = a0;

        if (NVST == 1 || nv == 1) {
            #pragma unroll 8
            for (int h = 0; h < 16; ++h) {
                float4 w = __ldg((const float4*)(Wp + (size_t)h * H));
                a0 = f4smad(v0s[h], w, a0);
            }
        } else if (nv == 2) {
            #pragma unroll 4
            for (int h = 0; h < 16; ++h) {
                float4 w = __ldg((const float4*)(Wp + (size_t)h * H));
                float s0 = v0s[h], s1 = v1s[h];
                a0 = f4smad(s0, w, a0);
                a1 = f4smad(s1, w, a1);
            }
        } else {
            #pragma unroll 4
            for (int h = 0; h < 16; ++h) {
                float4 w = __ldg((const float4*)(Wp + (size_t)h * H));
                float s0 = v0s[h], s1 = v1s[h], s2 = v2s[h];
                a0 = f4smad(s0, w, a0);
                a1 = f4smad(s1, w, a1);
                a2 = f4smad(s2, w, a2);
            }
        }

        smred[0][ty][tx] = a0;
        if (NVST > 1 && nv > 1) smred[1][ty][tx] = a1;
        if (NVST > 2 && nv > 2) smred[2][ty][tx] = a2;
        __syncthreads();

        #pragma unroll
        for (int s = 16; s > 0; s >>= 1) {
            if (ty < s) {
                #pragma unroll
                for (int vv = 0; vv < NVST; ++vv)
                    if (vv < nv)
                        smred[vv][ty][tx] = f4add(smred[vv][ty][tx], smred[vv][ty + s][tx]);
            }
            __syncthreads();
        }

        // write partials for this row-part
        if (ty == 0) {
            #pragma unroll
            for (int j = 0; j < NVST; ++j)
                if (j < nv)
                    *(float4*)(p.part + (size_t)(mslot0 + j) * 8 * 3 * H
                               + (size_t)rp * 3 * H + l * H + k0) = smred[j][0][tx];
            __threadfence();   // publish partials before ticket
        }
        __syncthreads();

        const int tid_tick = unit * 64 + kb;
        if (t == 0) sold = atomicAdd(&g_tick[tid_tick], 1);
        __syncthreads();

        if (sold == 7) {       // last row-part for this (unit, colblock): combine
            if (t < 64 * nv) {
                const int j = t >> 6, c = t & 63;
                const float* pb = p.part + (size_t)(mslot0 + j) * 8 * 3 * H
                                  + l * H + (kb << 6) + c;
                float acc = pb[0];
                #pragma unroll
                for (int rr = 1; rr < 8; ++rr) acc += pb[(size_t)rr * 3 * H];
                float* y = (j == 0) ? y0 : ((j == 1) ? y1 : y2);
                y[l * H + (kb << 6) + c] = acc;
            }
            if (t == 0) g_tick[tid_tick] = 0;   // self-reset for next stage/replay
        }
        __syncthreads();       // smred reuse on next tile
    }
}

// ---------------------------------------------------------------------------
// Final score_mix: h_next = mix(Lzh + Rz2h + b), cand3 = zhtil + z2h + b3.
// Also resets steal counters for the next run/replay.
// ---------------------------------------------------------------------------
__global__ void __launch_bounds__(1024) final_kernel(P p) {
    const int t = threadIdx.x;
    const int lane = t & 31, warp = t >> 5;
    __shared__ float red2[4][32];
    __shared__ float wsh[4];

    if (t < 8) g_ctr[t] = 0;

    float4 ws = ld4(p.Wsc, t);
    float4 cc[4];
    #pragma unroll
    for (int l = 0; l < 3; ++l)
        cc[l] = f4add(f4add(ld4(p.Lzh + l * H, t), ld4(p.Rz2h + l * H, t)), ld4(p.b + l * H, t));
    cc[3] = f4add(f4add(ld4(p.zhtil, t), ld4(p.z2h, t)), ld4(p.b + 3 * H, t));

    #pragma unroll
    for (int l = 0; l < 4; ++l) {
        float v = wred(dot4(cc[l], ws));
        if (lane == 0) red2[l][warp] = v;
    }
    __syncthreads();
    if (warp == 0) {
        float v[4];
        #pragma unroll
        for (int l = 0; l < 4; ++l) {
            v[l] = red2[l][lane];
            #pragma unroll
            for (int off = 16; off > 0; off >>= 1)
                v[l] += __shfl_down_sync(0xffffffffu, v[l], off);
        }
        if (lane == 0) {
            int amax = 0; float m1 = v[0];
            for (int l = 1; l < 4; ++l) if (v[l] > m1) { m1 = v[l]; amax = l; }
            float m2 = -INFINITY;
            for (int l = 0; l < 4; ++l) if (l != amax && v[l] > m2) m2 = v[l];
            float e[4], se = 0.f;
            for (int l = 0; l < 4; ++l) { e[l] = __expf(v[l] - m1); se += e[l]; }
            for (int l = 0; l < 4; ++l) wsh[l] = e[l] / se;
            p.out[4096 + 3 + 5] = (float)amax;
            p.out[4096 + 9 + 5] = m1 - m2;
        }
    }
    __syncthreads();

    float4 o = make_float4(0.f, 0.f, 0.f, 0.f);
    #pragma unroll
    for (int l = 0; l < 4; ++l) o = f4smad(wsh[l], cc[l], o);
    ((float4*)p.out)[t] = o;
}

// ---------------------------------------------------------------------------
// Launch sequence (graph-capturable: kernel launches only, default stream).
// ---------------------------------------------------------------------------
extern "C" void kernel_launch(void* const* d_in, const int* in_sizes, int n_in,
                              void* d_out_v, int out_size) {
    float* S = nullptr;
    cudaGetSymbolAddress((void**)&S, g_scratch);

    P p;
    p.L   = (const float*)d_in[2];
    p.R   = (const float*)d_in[3];
    p.x   = (const float*)d_in[0];
    p.hp  = (const float*)d_in[1];
    p.b   = (const float*)d_in[4];
    p.Wsc = (const float*)d_in[5];
    p.out = (float*)d_out_v;

    p.xL     = S + 0 * H;   p.hL     = S + 3 * H;   p.hR     = S + 6 * H;  // hR: 2H
    p.Rr     = S + 8 * H;   p.Rz1    = S + 11 * H;
    p.Rrh    = S + 14 * H;  p.RoneMZ = S + 17 * H;  p.Rz2h   = S + 20 * H;
    p.Lht    = S + 23 * H;  p.Lzh    = S + 26 * H;
    p.r      = S + 29 * H;  p.z1     = S + 30 * H;  p.rh     = S + 31 * H;
    p.oneMZ  = S + 32 * H;  p.z2h    = S + 33 * H;
    p.htilde = S + 34 * H;  p.zhtil  = S + 35 * H;
    p.part   = S + 36 * H;   // [3][8][3*H] = 72H

    const int DSM1 = 1 * H * (int)sizeof(float);   // 16KB
    const int DSM2 = 2 * H * (int)sizeof(float);   // 32KB
    const int DSM3 = 3 * H * (int)sizeof(float);   // 48KB
    cudaFuncSetAttribute(fused_kernel<0>, cudaFuncAttributeMaxDynamicSharedMemorySize, DSM2);
    cudaFuncSetAttribute(fused_kernel<1>, cudaFuncAttributeMaxDynamicSharedMemorySize, DSM2);
    cudaFuncSetAttribute(fused_kernel<2>, cudaFuncAttributeMaxDynamicSharedMemorySize, DSM3);
    cudaFuncSetAttribute(fused_kernel<3>, cudaFuncAttributeMaxDynamicSharedMemorySize, DSM1);
    cudaFuncSetAttribute(fused_kernel<4>, cudaFuncAttributeMaxDynamicSharedMemorySize, DSM1);

    dim3 blk(16, 32);

    fused_kernel<0><<<296, blk, DSM2>>>(p);  // A: L x {x,hp}, R x {hp}      320MB
    fused_kernel<1><<<296, blk, DSM2>>>(p);  // B: glue + R x {r,z1}         192MB
    fused_kernel<2><<<296, blk, DSM3>>>(p);  // C: 3-mix + R x {rh,oMZ,z2h}  192MB
    fused_kernel<3><<<296, blk, DSM1>>>(p);  // D: h_tilde + L x {htilde}    192MB
    fused_kernel<4><<<296, blk, DSM1>>>(p);  // E: zh_tilde + L x {zhtil}    192MB
    final_kernel<<<1, 1024>>>(p);            // F: h_next + counter reset
}

// round 9
// speedup vs baseline: 1.8069x; 1.1081x over previous
#include <cuda_runtime.h>
#include <math.h>

#define H 4096

// Scratch: finals (36H) + tile partials (60H = 320 tiles * 4 slots * 192).
__device__ float g_scratch[96 * H];
__device__ int g_tick[320];   // per-tile completion tickets, self-resetting

struct P {
    const float* L; const float* R;
    const float* x; const float* hp;
    const float* b; const float* Wsc;
    float* xL; float* hL; float* hR;          // hR: l=0..1 only
    float* Rr; float* Rz1;
    float* Rrh; float* RoneMZ; float* Rz2h;
    float* Lht; float* Lzh;
    float* r; float* z1; float* rh; float* oneMZ; float* z2h;
    float* htilde; float* zhtil;
    float* part;                               // [tile][4 slots][3][64]
    float* out;
};

// ---------------- helpers ----------------
__device__ __forceinline__ float4 f4add(float4 a, float4 b) {
    return make_float4(a.x + b.x, a.y + b.y, a.z + b.z, a.w + b.w);
}
__device__ __forceinline__ float4 f4fma(float4 a, float4 b, float4 c) {
    return make_float4(a.x * b.x + c.x, a.y * b.y + c.y, a.z * b.z + c.z, a.w * b.w + c.w);
}
__device__ __forceinline__ float4 f4smad(float s, float4 a, float4 acc) {
    return make_float4(s * a.x + acc.x, s * a.y + acc.y, s * a.z + acc.z, s * a.w + acc.w);
}
__device__ __forceinline__ float4 f4rsub1(float4 a) {
    return make_float4(1.f - a.x, 1.f - a.y, 1.f - a.z, 1.f - a.w);
}
__device__ __forceinline__ float ftanh(float x) { return 1.f - 2.f / (1.f + __expf(2.f * x)); }
__device__ __forceinline__ float fsig(float x)  { return 1.f / (1.f + __expf(-x)); }
__device__ __forceinline__ float4 f4tanh(float4 a) {
    return make_float4(ftanh(a.x), ftanh(a.y), ftanh(a.z), ftanh(a.w));
}
__device__ __forceinline__ float4 f4sig(float4 a) {
    return make_float4(fsig(a.x), fsig(a.y), fsig(a.z), fsig(a.w));
}
__device__ __forceinline__ float dot4(float4 a, float4 b) {
    return a.x * b.x + a.y * b.y + a.z * b.z + a.w * b.w;
}
__device__ __forceinline__ float4 ld4(const float* p, int i) {
    return __ldg(((const float4*)p) + i);
}
__device__ __forceinline__ float wred(float v) {
    v += __shfl_down_sync(0xffffffffu, v, 16);
    v += __shfl_down_sync(0xffffffffu, v, 8);
    v += __shfl_down_sync(0xffffffffu, v, 4);
    v += __shfl_down_sync(0xffffffffu, v, 2);
    v += __shfl_down_sync(0xffffffffu, v, 1);
    return v;
}

// Candidate values for the score_mix fused into stage MODE (2,3,4).
template<int MODE>
__device__ __forceinline__ void cands(const P& p, int idx, int l, float4* cc) {
    float4 b_ = ld4(p.b + l * H, idx);
    if (MODE == 2) {
        if (l < 3) {
            float4 hl = ld4(p.hL + l * H, idx);
            float4 rr = ld4(p.Rr + l * H, idx);
            float4 rz = ld4(p.Rz1 + l * H, idx);
            cc[0] = f4fma(hl, rr, b_);
            cc[1] = f4rsub1(f4add(rz, b_));
            cc[2] = f4fma(hl, rz, b_);
        } else {
            float4 hp4 = ld4(p.hp, idx);
            float4 r4  = ld4(p.r, idx);
            float4 z4  = ld4(p.z1, idx);
            cc[0] = f4fma(hp4, r4, b_);
            cc[1] = f4rsub1(f4add(z4, b_));
            cc[2] = f4fma(hp4, z4, b_);
        }
    } else if (MODE == 3) {
        if (l < 3)
            cc[0] = f4tanh(f4add(f4add(ld4(p.xL + l * H, idx), ld4(p.Rrh + l * H, idx)), b_));
        else
            cc[0] = f4tanh(f4add(f4add(ld4(p.x, idx), ld4(p.rh, idx)), b_));
    } else {  // MODE == 4
        if (l < 3)
            cc[0] = f4fma(ld4(p.Lht + l * H, idx), ld4(p.RoneMZ + l * H, idx), b_);
        else
            cc[0] = f4fma(ld4(p.htilde, idx), ld4(p.oneMZ, idx), b_);
    }
}

// ---------------------------------------------------------------------------
// Fused kernel: [prologue -> vsm] + balanced static streaming matvec.
// Block (16,32)=512 thr, grid 296 (2 blocks/SM, all slots filled).
// Work = NTILE col-tiles (64 cols x full H) x 32 row-chunks (128 rows).
// Block i statically owns chunks [i*R/296, (i+1)*R/296) -> <=5% imbalance,
// spans <=3 col tiles -> <=3 segments, each 80-128 loads/thread between
// barriers (R4 granularity). Cross-block sums: fixed partial slots + ticket
// atomic; last finisher combines slots in fixed order (deterministic).
// MODE 0: A  NTILE=320 (L x {x,hp} l=0..2 ; R x {hp} l=0..1)
// MODE 1: B  NTILE=192 (sigmoid glue; R x {r,z1})
// MODE 2: C  NTILE=192 (3-way score_mix; R x {rh,oneMZ,z2h})
// MODE 3: D  NTILE=192 (h_tilde mix; L x {htilde})
// MODE 4: E  NTILE=192 (zh_tilde mix; L x {zhtil})
// ---------------------------------------------------------------------------
template<int MODE>
__global__ void __launch_bounds__(512, 2) fused_kernel(P p) {
    extern __shared__ float vsm[];                 // [NVST][H] input vectors
    constexpr int NVST = (MODE == 2) ? 3 : ((MODE == 3 || MODE == 4) ? 1 : 2);
    constexpr int NTILE = (MODE == 0) ? 320 : 192;
    __shared__ float4 smred[NVST][32][16];
    __shared__ float red[12][16];
    __shared__ float wsm[3][4];
    __shared__ int sold;

    const int tx = threadIdx.x, ty = threadIdx.y;  // 16 x 32
    const int t = ty * 16 + tx;
    const int lane = t & 31, warp = t >> 5;
    const int bx = blockIdx.x;
    const long long G = gridDim.x;                 // 296

    // ---------------- prologue: fill vsm ----------------
    if (MODE == 0) {
        #pragma unroll
        for (int c = 0; c < 2; ++c) {
            int idx = t + c * 512;
            ((float4*)vsm)[idx]       = ld4(p.x, idx);
            ((float4*)(vsm + H))[idx] = ld4(p.hp, idx);
        }
        __syncthreads();
    } else if (MODE == 1) {
        #pragma unroll
        for (int c = 0; c < 2; ++c) {
            int idx = t + c * 512;
            float4 z14 = f4sig(f4add(f4add(ld4(p.xL, idx),     ld4(p.hR, idx)),     ld4(p.b, idx)));
            float4 r4  = f4sig(f4add(f4add(ld4(p.xL + H, idx), ld4(p.hR + H, idx)), ld4(p.b + H, idx)));
            ((float4*)vsm)[idx]       = r4;    // v0 = r
            ((float4*)(vsm + H))[idx] = z14;   // v1 = z1
            if (bx == 0) {
                ((float4*)p.r)[idx]  = r4;
                ((float4*)p.z1)[idx] = z14;
            }
        }
        if (bx == 0 && t < 3) p.out[4096 + t] = (t == 1) ? 1.f : 0.f;
        __syncthreads();
    } else {
        constexpr int NM = (MODE == 2) ? 3 : 1;
        float s[NM * 4];
        #pragma unroll
        for (int d = 0; d < NM * 4; ++d) s[d] = 0.f;

        #pragma unroll
        for (int c = 0; c < 2; ++c) {
            int idx = t + c * 512;
            float4 ws = ld4(p.Wsc, idx);
            #pragma unroll
            for (int ll = 0; ll < 4; ++ll) {
                float4 cc[NM];
                cands<MODE>(p, idx, ll, cc);
                #pragma unroll
                for (int m = 0; m < NM; ++m) s[m * 4 + ll] += dot4(cc[m], ws);
            }
        }
        #pragma unroll
        for (int d = 0; d < NM * 4; ++d) {
            float v = wred(s[d]);
            if (lane == 0) red[d][warp] = v;
        }
        __syncthreads();
        if (t == 0) {
            #pragma unroll
            for (int m = 0; m < NM; ++m) {
                float sc[4];
                #pragma unroll
                for (int l2 = 0; l2 < 4; ++l2) {
                    float a = 0.f;
                    #pragma unroll
                    for (int w2 = 0; w2 < 16; ++w2) a += red[m * 4 + l2][w2];
                    sc[l2] = a;
                }
                int amax = 0; float m1 = sc[0];
                for (int l2 = 1; l2 < 4; ++l2) if (sc[l2] > m1) { m1 = sc[l2]; amax = l2; }
                float m2 = -INFINITY;
                for (int l2 = 0; l2 < 4; ++l2) if (l2 != amax && sc[l2] > m2) m2 = sc[l2];
                float e[4], se = 0.f;
                for (int l2 = 0; l2 < 4; ++l2) { e[l2] = __expf(sc[l2] - m1); se += e[l2]; }
                for (int l2 = 0; l2 < 4; ++l2) wsm[m][l2] = e[l2] / se;
                if (bx == 0) {
                    int slot = (MODE == 2) ? (m * 2) : ((MODE == 3) ? 1 : 3);
                    p.out[4096 + 3 + slot] = (float)amax;
                    p.out[4096 + 9 + slot] = m1 - m2;
                }
            }
        }
        __syncthreads();

        float* gv[NM];
        if (MODE == 2) { gv[0] = p.rh; gv[1] = p.oneMZ; gv[2] = p.z2h; }
        if (MODE == 3) { gv[0] = p.htilde; }
        if (MODE == 4) { gv[0] = p.zhtil; }
        #pragma unroll
        for (int c = 0; c < 2; ++c) {
            int idx = t + c * 512;
            float4 v[NM];
            #pragma unroll
            for (int m = 0; m < NM; ++m) v[m] = make_float4(0.f, 0.f, 0.f, 0.f);
            #pragma unroll
            for (int ll = 0; ll < 4; ++ll) {
                float4 cc[NM];
                cands<MODE>(p, idx, ll, cc);
                #pragma unroll
                for (int m = 0; m < NM; ++m) v[m] = f4smad(wsm[m][ll], cc[m], v[m]);
            }
            #pragma unroll
            for (int m = 0; m < NM; ++m) {
                ((float4*)(vsm + m * H))[idx] = v[m];
                if (bx == 0) ((float4*)gv[m])[idx] = v[m];
            }
        }
        __syncthreads();
    }

    // ---------------- balanced static streaming matvec ----------------
    const long long Rch = (long long)NTILE * 32;   // total 128-row chunks
    long long cchunk = (long long)bx * Rch / G;
    const long long c_end = ((long long)bx + 1) * Rch / G;

    while (cchunk < c_end) {
        const int tile = (int)(cchunk >> 5);
        const long long segend_ll = min(c_end, (long long)(tile + 1) << 5);
        const int nch = (int)(segend_ll - cchunk);         // 1..32 chunks
        const int row0 = ((int)cchunk & 31) << 7;

        // decode tile -> unit / outputs
        const int unit = tile >> 6;
        const int kb = tile & 63;
        int l, nv;
        const float* W;
        float *y0 = nullptr, *y1 = nullptr, *y2 = nullptr;
        const float *v0 = vsm, *v1 = vsm + H, *v2 = vsm + 2 * H;
        if (MODE == 0) {
            if (unit < 3) { W = p.L; l = unit;     nv = 2; y0 = p.xL; y1 = p.hL; }
            else          { W = p.R; l = unit - 3; nv = 1; y0 = p.hR; v0 = vsm + H; }
        } else {
            l = unit;
            nv = (MODE == 2) ? 3 : ((MODE == 1) ? 2 : 1);
            if (MODE == 1) { W = p.R; y0 = p.Rr;  y1 = p.Rz1; }
            if (MODE == 2) { W = p.R; y0 = p.Rrh; y1 = p.RoneMZ; y2 = p.Rz2h; }
            if (MODE == 3) { W = p.L; y0 = p.Lht; }
            if (MODE == 4) { W = p.L; y0 = p.Lzh; }
        }

        const int k0 = (kb << 6) + (tx << 2);
        const int rpt = nch << 2;                    // rows per ty slice
        const int h0 = row0 + ty * rpt;
        const float* __restrict__ Wp = W + (size_t)l * H * H + (size_t)h0 * H + k0;
        const float* v0s = v0 + h0;
        const float* v1s = v1 + h0;
        const float* v2s = v2 + h0;
        float4 a0 = make_float4(0.f, 0.f, 0.f, 0.f), a1 = a0, a2 = a0;

        if (NVST == 1 || nv == 1) {
            #pragma unroll 4
            for (int h = 0; h < rpt; ++h) {
                float4 w = __ldg((const float4*)(Wp + (size_t)h * H));
                a0 = f4smad(v0s[h], w, a0);
            }
        } else if (nv == 2) {
            #pragma unroll 4
            for (int h = 0; h < rpt; ++h) {
                float4 w = __ldg((const float4*)(Wp + (size_t)h * H));
                float s0 = v0s[h], s1 = v1s[h];
                a0 = f4smad(s0, w, a0);
                a1 = f4smad(s1, w, a1);
            }
        } else {
            #pragma unroll 4
            for (int h = 0; h < rpt; ++h) {
                float4 w = __ldg((const float4*)(Wp + (size_t)h * H));
                float s0 = v0s[h], s1 = v1s[h], s2 = v2s[h];
                a0 = f4smad(s0, w, a0);
                a1 = f4smad(s1, w, a1);
                a2 = f4smad(s2, w, a2);
            }
        }

        smred[0][ty][tx] = a0;
        if (NVST > 1 && nv > 1) smred[1][ty][tx] = a1;
        if (NVST > 2 && nv > 2) smred[2][ty][tx] = a2;
        __syncthreads();

        #pragma unroll
        for (int s = 16; s > 0; s >>= 1) {
            if (ty < s) {
                #pragma unroll
                for (int vv = 0; vv < NVST; ++vv)
                    if (vv < nv)
                        smred[vv][ty][tx] = f4add(smred[vv][ty][tx], smred[vv][ty + s][tx]);
            }
            __syncthreads();
        }

        // slot/contributor arithmetic (fixed by static partition)
        const long long tc0 = (long long)tile << 5;
        const int i_first = (int)(((tc0 + 1) * G - 1) / Rch);
        const int i_last  = (int)(((tc0 + 32) * G - 1) / Rch);
        const int n_c = i_last - i_first + 1;
        const int slot = bx - i_first;

        if (n_c == 1) {
            // sole contributor: write final directly
            if (ty == 0) {
                if (nv > 0) *(float4*)(y0 + l * H + k0) = smred[0][0][tx];
                if (NVST > 1 && nv > 1) *(float4*)(y1 + l * H + k0) = smred[1][0][tx];
                if (NVST > 2 && nv > 2) *(float4*)(y2 + l * H + k0) = smred[2][0][tx];
            }
        } else {
            if (ty == 0) {
                float* pp = p.part + (size_t)tile * 768 + (size_t)slot * 192;
                *(float4*)(pp + (tx << 2)) = smred[0][0][tx];
                if (NVST > 1 && nv > 1) *(float4*)(pp + 64 + (tx << 2)) = smred[1][0][tx];
                if (NVST > 2 && nv > 2) *(float4*)(pp + 128 + (tx << 2)) = smred[2][0][tx];
            }
            __threadfence();
            __syncthreads();
            if (t == 0) sold = atomicAdd(&g_tick[tile], 1);
            __syncthreads();
            if (sold == n_c - 1) {
                __threadfence();
                if (t < 64 * nv) {
                    const int j = t >> 6, c2 = t & 63;
                    const float* pb = p.part + (size_t)tile * 768 + j * 64 + c2;
                    float acc = 0.f;
                    for (int s2 = 0; s2 < n_c; ++s2) acc += __ldcg(pb + s2 * 192);
                    float* y = (j == 0) ? y0 : ((j == 1) ? y1 : y2);
                    y[l * H + (kb << 6) + c2] = acc;
                }
                if (t == 0) g_tick[tile] = 0;   // self-reset (replay-safe)
            }
        }
        __syncthreads();   // smred reuse next segment
        cchunk = segend_ll;
    }
}

// ---------------------------------------------------------------------------
// Final score_mix: h_next = mix(Lzh + Rz2h + b), cand3 = zhtil + z2h + b3.
// ---------------------------------------------------------------------------
__global__ void __launch_bounds__(1024) final_kernel(P p) {
    const int t = threadIdx.x;
    const int lane = t & 31, warp = t >> 5;
    __shared__ float red2[4][32];
    __shared__ float wsh[4];

    float4 ws = ld4(p.Wsc, t);
    float4 cc[4];
    #pragma unroll
    for (int l = 0; l < 3; ++l)
        cc[l] = f4add(f4add(ld4(p.Lzh + l * H, t), ld4(p.Rz2h + l * H, t)), ld4(p.b + l * H, t));
    cc[3] = f4add(f4add(ld4(p.zhtil, t), ld4(p.z2h, t)), ld4(p.b + 3 * H, t));

    #pragma unroll
    for (int l = 0; l < 4; ++l) {
        float v = wred(dot4(cc[l], ws));
        if (lane == 0) red2[l][warp] = v;
    }
    __syncthreads();
    if (warp == 0) {
        float v[4];
        #pragma unroll
        for (int l = 0; l < 4; ++l) {
            v[l] = red2[l][lane];
            #pragma unroll
            for (int off = 16; off > 0; off >>= 1)
                v[l] += __shfl_down_sync(0xffffffffu, v[l], off);
        }
        if (lane == 0) {
            int amax = 0; float m1 = v[0];
            for (int l = 1; l < 4; ++l) if (v[l] > m1) { m1 = v[l]; amax = l; }
            float m2 = -INFINITY;
            for (int l = 0; l < 4; ++l) if (l != amax && v[l] > m2) m2 = v[l];
            float e[4], se = 0.f;
            for (int l = 0; l < 4; ++l) { e[l] = __expf(v[l] - m1); se += e[l]; }
            for (int l = 0; l < 4; ++l) wsh[l] = e[l] / se;
            p.out[4096 + 3 + 5] = (float)amax;
            p.out[4096 + 9 + 5] = m1 - m2;
        }
    }
    __syncthreads();

    float4 o = make_float4(0.f, 0.f, 0.f, 0.f);
    #pragma unroll
    for (int l = 0; l < 4; ++l) o = f4smad(wsh[l], cc[l], o);
    ((float4*)p.out)[t] = o;
}

// ---------------------------------------------------------------------------
// Launch sequence (graph-capturable: kernel launches only, default stream).
// ---------------------------------------------------------------------------
extern "C" void kernel_launch(void* const* d_in, const int* in_sizes, int n_in,
                              void* d_out_v, int out_size) {
    float* S = nullptr;
    cudaGetSymbolAddress((void**)&S, g_scratch);

    P p;
    p.L   = (const float*)d_in[2];
    p.R   = (const float*)d_in[3];
    p.x   = (const float*)d_in[0];
    p.hp  = (const float*)d_in[1];
    p.b   = (const float*)d_in[4];
    p.Wsc = (const float*)d_in[5];
    p.out = (float*)d_out_v;

    p.xL     = S + 0 * H;   p.hL     = S + 3 * H;   p.hR     = S + 6 * H;  // hR: 2H
    p.Rr     = S + 8 * H;   p.Rz1    = S + 11 * H;
    p.Rrh    = S + 14 * H;  p.RoneMZ = S + 17 * H;  p.Rz2h   = S + 20 * H;
    p.Lht    = S + 23 * H;  p.Lzh    = S + 26 * H;
    p.r      = S + 29 * H;  p.z1     = S + 30 * H;  p.rh     = S + 31 * H;
    p.oneMZ  = S + 32 * H;  p.z2h    = S + 33 * H;
    p.htilde = S + 34 * H;  p.zhtil  = S + 35 * H;
    p.part   = S + 36 * H;   // [320 tiles][4 slots][3][64] = 60H

    const int DSM1 = 1 * H * (int)sizeof(float);   // 16KB
    const int DSM2 = 2 * H * (int)sizeof(float);   // 32KB
    const int DSM3 = 3 * H * (int)sizeof(float);   // 48KB
    cudaFuncSetAttribute(fused_kernel<0>, cudaFuncAttributeMaxDynamicSharedMemorySize, DSM2);
    cudaFuncSetAttribute(fused_kernel<1>, cudaFuncAttributeMaxDynamicSharedMemorySize, DSM2);
    cudaFuncSetAttribute(fused_kernel<2>, cudaFuncAttributeMaxDynamicSharedMemorySize, DSM3);
    cudaFuncSetAttribute(fused_kernel<3>, cudaFuncAttributeMaxDynamicSharedMemorySize, DSM1);
    cudaFuncSetAttribute(fused_kernel<4>, cudaFuncAttributeMaxDynamicSharedMemorySize, DSM1);

    dim3 blk(16, 32);

    fused_kernel<0><<<296, blk, DSM2>>>(p);  // A: L x {x,hp}, R x {hp}      320MB
    fused_kernel<1><<<296, blk, DSM2>>>(p);  // B: glue + R x {r,z1}         192MB
    fused_kernel<2><<<296, blk, DSM3>>>(p);  // C: 3-mix + R x {rh,oMZ,z2h}  192MB
    fused_kernel<3><<<296, blk, DSM1>>>(p);  // D: h_tilde + L x {htilde}    192MB
    fused_kernel<4><<<296, blk, DSM1>>>(p);  // E: zh_tilde + L x {zhtil}    192MB
    final_kernel<<<1, 1024>>>(p);            // F: h_next
}

// round 10
// speedup vs baseline: 1.8874x; 1.0446x over previous
#include <cuda_runtime.h>
#include <math.h>

#define H 4096

// Scratch: finals (36H) + split-tile partials (~40K floats).
__device__ float g_scratch[47 * H];
__device__ int g_tick[320];   // per-tile completion tickets, self-resetting

struct P {
    const float* L; const float* R;
    const float* x; const float* hp;
    const float* b; const float* Wsc;
    float* xL; float* hL; float* hR;          // hR: l=0..1 only
    float* Rr; float* Rz1;
    float* Rrh; float* RoneMZ; float* Rz2h;
    float* Lht; float* Lzh;
    float* r; float* z1; float* rh; float* oneMZ; float* z2h;
    float* htilde; float* zhtil;
    float* part;                               // split-tile partials
    float* out;
};

// ---------------- helpers ----------------
__device__ __forceinline__ float4 f4add(float4 a, float4 b) {
    return make_float4(a.x + b.x, a.y + b.y, a.z + b.z, a.w + b.w);
}
__device__ __forceinline__ float4 f4fma(float4 a, float4 b, float4 c) {
    return make_float4(a.x * b.x + c.x, a.y * b.y + c.y, a.z * b.z + c.z, a.w * b.w + c.w);
}
__device__ __forceinline__ float4 f4smad(float s, float4 a, float4 acc) {
    return make_float4(s * a.x + acc.x, s * a.y + acc.y, s * a.z + acc.z, s * a.w + acc.w);
}
__device__ __forceinline__ float4 f4rsub1(float4 a) {
    return make_float4(1.f - a.x, 1.f - a.y, 1.f - a.z, 1.f - a.w);
}
__device__ __forceinline__ float ftanh(float x) { return 1.f - 2.f / (1.f + __expf(2.f * x)); }
__device__ __forceinline__ float fsig(float x)  { return 1.f / (1.f + __expf(-x)); }
__device__ __forceinline__ float4 f4tanh(float4 a) {
    return make_float4(ftanh(a.x), ftanh(a.y), ftanh(a.z), ftanh(a.w));
}
__device__ __forceinline__ float4 f4sig(float4 a) {
    return make_float4(fsig(a.x), fsig(a.y), fsig(a.z), fsig(a.w));
}
__device__ __forceinline__ float dot4(float4 a, float4 b) {
    return a.x * b.x + a.y * b.y + a.z * b.z + a.w * b.w;
}
__device__ __forceinline__ float4 ld4(const float* p, int i) {
    return __ldg(((const float4*)p) + i);
}
__device__ __forceinline__ float wred(float v) {
    v += __shfl_down_sync(0xffffffffu, v, 16);
    v += __shfl_down_sync(0xffffffffu, v, 8);
    v += __shfl_down_sync(0xffffffffu, v, 4);
    v += __shfl_down_sync(0xffffffffu, v, 2);
    v += __shfl_down_sync(0xffffffffu, v, 1);
    return v;
}

// Candidate values for the score_mix fused into stage MODE (2,3,4).
template<int MODE>
__device__ __forceinline__ void cands(const P& p, int idx, int l, float4* cc) {
    float4 b_ = ld4(p.b + l * H, idx);
    if (MODE == 2) {
        if (l < 3) {
            float4 hl = ld4(p.hL + l * H, idx);
            float4 rr = ld4(p.Rr + l * H, idx);
            float4 rz = ld4(p.Rz1 + l * H, idx);
            cc[0] = f4fma(hl, rr, b_);
            cc[1] = f4rsub1(f4add(rz, b_));
            cc[2] = f4fma(hl, rz, b_);
        } else {
            float4 hp4 = ld4(p.hp, idx);
            float4 r4  = ld4(p.r, idx);
            float4 z4  = ld4(p.z1, idx);
            cc[0] = f4fma(hp4, r4, b_);
            cc[1] = f4rsub1(f4add(z4, b_));
            cc[2] = f4fma(hp4, z4, b_);
        }
    } else if (MODE == 3) {
        if (l < 3)
            cc[0] = f4tanh(f4add(f4add(ld4(p.xL + l * H, idx), ld4(p.Rrh + l * H, idx)), b_));
        else
            cc[0] = f4tanh(f4add(f4add(ld4(p.x, idx), ld4(p.rh, idx)), b_));
    } else {  // MODE == 4
        if (l < 3)
            cc[0] = f4fma(ld4(p.Lht + l * H, idx), ld4(p.RoneMZ + l * H, idx), b_);
        else
            cc[0] = f4fma(ld4(p.htilde, idx), ld4(p.oneMZ, idx), b_);
    }
}

// Static-trip-count streaming inner loop (R4-proven pattern).
template<int NVST, int RPT>
__device__ __forceinline__ void run_mv(const float* __restrict__ Wp,
                                       const float* v0s, const float* v1s, const float* v2s,
                                       int nv, float4& a0, float4& a1, float4& a2) {
    float4 x0 = make_float4(0.f, 0.f, 0.f, 0.f), x1 = x0, x2 = x0;
    if (NVST == 1 || nv == 1) {
        #pragma unroll 8
        for (int h = 0; h < RPT; ++h) {
            float4 w = __ldg((const float4*)(Wp + (size_t)h * H));
            x0 = f4smad(v0s[h], w, x0);
        }
    } else if (nv == 2) {
        #pragma unroll 4
        for (int h = 0; h < RPT; ++h) {
            float4 w = __ldg((const float4*)(Wp + (size_t)h * H));
            float s0 = v0s[h], s1 = v1s[h];
            x0 = f4smad(s0, w, x0);
            x1 = f4smad(s1, w, x1);
        }
    } else {
        #pragma unroll 4
        for (int h = 0; h < RPT; ++h) {
            float4 w = __ldg((const float4*)(Wp + (size_t)h * H));
            float s0 = v0s[h], s1 = v1s[h], s2 = v2s[h];
            x0 = f4smad(s0, w, x0);
            x1 = f4smad(s1, w, x1);
            x2 = f4smad(s2, w, x2);
        }
    }
    a0 = x0; a1 = x1; a2 = x2;
}

// ---------------------------------------------------------------------------
// Fused kernel: [prologue -> vsm] + R4-style streaming matvec with a STATIC
// pair-aware 3-way split. Block (16,32)=512 thr, grid 296 (blocks b and b+148
// share an SM via the classic-launch LUT, so work is assigned to equalize
// pair sums). Split tiles combine via tickets (fixed-order, deterministic).
// MODE 0: A (tiles 0..319; blocks 0..295 full tiles, blocks 0..191 also take
//         one 512-row eighth of tiles 296..319)
// MODE 1..4: B..E (tiles 0..191: blocks 0..103 top half of tiles 0..103,
//         blocks 104..191 full tiles, blocks 192..295 bottom half of 0..103)
// ---------------------------------------------------------------------------
template<int MODE>
__global__ void __launch_bounds__(512, 2) fused_kernel(P p) {
    extern __shared__ float vsm[];                 // [NVST][H] input vectors
    constexpr int NVST = (MODE == 2) ? 3 : ((MODE == 3 || MODE == 4) ? 1 : 2);
    __shared__ float4 smred[NVST][32][16];
    __shared__ float red[12][16];
    __shared__ float wsm[3][4];
    __shared__ int sold;

    const int tx = threadIdx.x, ty = threadIdx.y;  // 16 x 32
    const int t = ty * 16 + tx;
    const int lane = t & 31, warp = t >> 5;
    const int bx = blockIdx.x;

    // ---------------- prologue: fill vsm ----------------
    if (MODE == 0) {
        #pragma unroll
        for (int c = 0; c < 2; ++c) {
            int idx = t + c * 512;
            ((float4*)vsm)[idx]       = ld4(p.x, idx);
            ((float4*)(vsm + H))[idx] = ld4(p.hp, idx);
        }
        __syncthreads();
    } else if (MODE == 1) {
        #pragma unroll
        for (int c = 0; c < 2; ++c) {
            int idx = t + c * 512;
            float4 z14 = f4sig(f4add(f4add(ld4(p.xL, idx),     ld4(p.hR, idx)),     ld4(p.b, idx)));
            float4 r4  = f4sig(f4add(f4add(ld4(p.xL + H, idx), ld4(p.hR + H, idx)), ld4(p.b + H, idx)));
            ((float4*)vsm)[idx]       = r4;    // v0 = r
            ((float4*)(vsm + H))[idx] = z14;   // v1 = z1
            if (bx == 0) {
                ((float4*)p.r)[idx]  = r4;
                ((float4*)p.z1)[idx] = z14;
            }
        }
        if (bx == 0 && t < 3) p.out[4096 + t] = (t == 1) ? 1.f : 0.f;
        __syncthreads();
    } else {
        constexpr int NM = (MODE == 2) ? 3 : 1;
        float s[NM * 4];
        #pragma unroll
        for (int d = 0; d < NM * 4; ++d) s[d] = 0.f;

        #pragma unroll
        for (int c = 0; c < 2; ++c) {
            int idx = t + c * 512;
            float4 ws = ld4(p.Wsc, idx);
            #pragma unroll
            for (int ll = 0; ll < 4; ++ll) {
                float4 cc[NM];
                cands<MODE>(p, idx, ll, cc);
                #pragma unroll
                for (int m = 0; m < NM; ++m) s[m * 4 + ll] += dot4(cc[m], ws);
            }
        }
        #pragma unroll
        for (int d = 0; d < NM * 4; ++d) {
            float v = wred(s[d]);
            if (lane == 0) red[d][warp] = v;
        }
        __syncthreads();
        if (t == 0) {
            #pragma unroll
            for (int m = 0; m < NM; ++m) {
                float sc[4];
                #pragma unroll
                for (int l2 = 0; l2 < 4; ++l2) {
                    float a = 0.f;
                    #pragma unroll
                    for (int w2 = 0; w2 < 16; ++w2) a += red[m * 4 + l2][w2];
                    sc[l2] = a;
                }
                int amax = 0; float m1 = sc[0];
                for (int l2 = 1; l2 < 4; ++l2) if (sc[l2] > m1) { m1 = sc[l2]; amax = l2; }
                float m2 = -INFINITY;
                for (int l2 = 0; l2 < 4; ++l2) if (l2 != amax && sc[l2] > m2) m2 = sc[l2];
                float e[4], se = 0.f;
                for (int l2 = 0; l2 < 4; ++l2) { e[l2] = __expf(sc[l2] - m1); se += e[l2]; }
                for (int l2 = 0; l2 < 4; ++l2) wsm[m][l2] = e[l2] / se;
                if (bx == 0) {
                    int slot = (MODE == 2) ? (m * 2) : ((MODE == 3) ? 1 : 3);
                    p.out[4096 + 3 + slot] = (float)amax;
                    p.out[4096 + 9 + slot] = m1 - m2;
                }
            }
        }
        __syncthreads();

        float* gv[NM];
        if (MODE == 2) { gv[0] = p.rh; gv[1] = p.oneMZ; gv[2] = p.z2h; }
        if (MODE == 3) { gv[0] = p.htilde; }
        if (MODE == 4) { gv[0] = p.zhtil; }
        #pragma unroll
        for (int c = 0; c < 2; ++c) {
            int idx = t + c * 512;
            float4 v[NM];
            #pragma unroll
            for (int m = 0; m < NM; ++m) v[m] = make_float4(0.f, 0.f, 0.f, 0.f);
            #pragma unroll
            for (int ll = 0; ll < 4; ++ll) {
                float4 cc[NM];
                cands<MODE>(p, idx, ll, cc);
                #pragma unroll
                for (int m = 0; m < NM; ++m) v[m] = f4smad(wsm[m][ll], cc[m], v[m]);
            }
            #pragma unroll
            for (int m = 0; m < NM; ++m) {
                ((float4*)(vsm + m * H))[idx] = v[m];
                if (bx == 0) ((float4*)gv[m])[idx] = v[m];
            }
        }
        __syncthreads();
    }

    // ---------------- segment decode ----------------
    // seg 1 for all blocks; MODE 0 adds a small seg 2 (eighth-pieces).
    for (int seg = 0; seg < 2; ++seg) {
        int tile, rowbase, rptc, contrib;   // rptc: 0=128 rows/thr, 1=64, 2=16
        if (seg == 0) {
            if (MODE == 0)            { tile = bx;        rowbase = 0;    rptc = 0; contrib = -1; }
            else if (bx < 104)        { tile = bx;        rowbase = 0;    rptc = 1; contrib = 0; }
            else if (bx < 192)        { tile = bx;        rowbase = 0;    rptc = 0; contrib = -1; }
            else                      { tile = bx - 192;  rowbase = 2048; rptc = 1; contrib = 1; }
        } else {
            if (MODE != 0 || bx >= 192) break;
            tile = 296 + (bx >> 3); rowbase = (bx & 7) * 512; rptc = 2; contrib = bx & 7;
        }

        // decode tile -> unit/outputs (R4 decode)
        const int unit = tile >> 6;
        const int kb = tile & 63;
        int l, nv;
        const float* W;
        float *y0 = nullptr, *y1 = nullptr, *y2 = nullptr;
        const float *v0 = vsm, *v1 = vsm + H, *v2 = vsm + 2 * H;
        if (MODE == 0) {
            if (unit < 3) { W = p.L; l = unit;     nv = 2; y0 = p.xL; y1 = p.hL; }
            else          { W = p.R; l = unit - 3; nv = 1; y0 = p.hR; v0 = vsm + H; }
        } else {
            l = unit;
            nv = (MODE == 2) ? 3 : ((MODE == 1) ? 2 : 1);
            if (MODE == 1) { W = p.R; y0 = p.Rr;  y1 = p.Rz1; }
            if (MODE == 2) { W = p.R; y0 = p.Rrh; y1 = p.RoneMZ; y2 = p.Rz2h; }
            if (MODE == 3) { W = p.L; y0 = p.Lht; }
            if (MODE == 4) { W = p.L; y0 = p.Lzh; }
        }

        const int k0 = (kb << 6) + (tx << 2);
        const int rpt = (rptc == 0) ? 128 : ((rptc == 1) ? 64 : 16);
        const int h0 = rowbase + ty * rpt;
        const float* __restrict__ Wp = W + (size_t)l * H * H + (size_t)h0 * H + k0;
        float4 a0, a1, a2;
        if (rptc == 0)      run_mv<NVST, 128>(Wp, v0 + h0, v1 + h0, v2 + h0, nv, a0, a1, a2);
        else if (rptc == 1) run_mv<NVST, 64>(Wp, v0 + h0, v1 + h0, v2 + h0, nv, a0, a1, a2);
        else                run_mv<NVST, 16>(Wp, v0 + h0, v1 + h0, v2 + h0, nv, a0, a1, a2);

        if (seg == 1) __syncthreads();   // smred reuse
        smred[0][ty][tx] = a0;
        if (NVST > 1 && nv > 1) smred[1][ty][tx] = a1;
        if (NVST > 2 && nv > 2) smred[2][ty][tx] = a2;
        __syncthreads();

        #pragma unroll
        for (int s = 16; s > 0; s >>= 1) {
            if (ty < s) {
                #pragma unroll
                for (int vv = 0; vv < NVST; ++vv)
                    if (vv < nv)
                        smred[vv][ty][tx] = f4add(smred[vv][ty][tx], smred[vv][ty + s][tx]);
            }
            __syncthreads();
        }

        if (contrib < 0) {
            // sole contributor: final write
            if (ty == 0) {
                *(float4*)(y0 + l * H + k0) = smred[0][0][tx];
                if (NVST > 1 && nv > 1) *(float4*)(y1 + l * H + k0) = smred[1][0][tx];
                if (NVST > 2 && nv > 2) *(float4*)(y2 + l * H + k0) = smred[2][0][tx];
            }
        } else if (MODE != 0) {
            // B..E split tile: 2 contributors. part[(contrib*3+j)*104+tile][64]
            if (ty == 0) {
                #pragma unroll
                for (int j = 0; j < NVST; ++j)
                    if (j < nv)
                        *(float4*)(p.part + (((contrib * 3 + j) * 104 + tile) << 6) + (tx << 2))
                            = smred[j][0][tx];
                __threadfence();
            }
            __syncthreads();
            if (t == 0) sold = atomicAdd(&g_tick[tile], 1);
            __syncthreads();
            if (sold == 1) {
                __threadfence();
                if (t < 64 * nv) {
                    const int j = t >> 6, c2 = t & 63;
                    float a = __ldcg(p.part + (((0 * 3 + j) * 104 + tile) << 6) + c2)
                            + __ldcg(p.part + (((1 * 3 + j) * 104 + tile) << 6) + c2);
                    float* y = (j == 0) ? y0 : ((j == 1) ? y1 : y2);
                    y[l * H + (kb << 6) + c2] = a;
                }
                if (t == 0) g_tick[tile] = 0;
            }
            __syncthreads();
        } else {
            // A eighth-piece: 8 contributors, nv=1 (unit 4). part[(contrib*24+pt)][64]
            const int pt = tile - 296;
            if (ty == 0) {
                *(float4*)(p.part + ((contrib * 24 + pt) << 6) + (tx << 2)) = smred[0][0][tx];
                __threadfence();
            }
            __syncthreads();
            if (t == 0) sold = atomicAdd(&g_tick[tile], 1);
            __syncthreads();
            if (sold == 7) {
                __threadfence();
                if (t < 64) {
                    float a = 0.f;
                    #pragma unroll
                    for (int c8 = 0; c8 < 8; ++c8)
                        a += __ldcg(p.part + ((c8 * 24 + pt) << 6) + t);
                    y0[l * H + (kb << 6) + t] = a;
                }
                if (t == 0) g_tick[tile] = 0;
            }
            __syncthreads();
        }
    }
}

// ---------------------------------------------------------------------------
// Final score_mix: h_next = mix(Lzh + Rz2h + b), cand3 = zhtil + z2h + b3.
// ---------------------------------------------------------------------------
__global__ void __launch_bounds__(1024) final_kernel(P p) {
    const int t = threadIdx.x;
    const int lane = t & 31, warp = t >> 5;
    __shared__ float red2[4][32];
    __shared__ float wsh[4];

    if (t < 320) g_tick[t] = 0;   // belt: tickets already self-reset

    float4 ws = ld4(p.Wsc, t);
    float4 cc[4];
    #pragma unroll
    for (int l = 0; l < 3; ++l)
        cc[l] = f4add(f4add(ld4(p.Lzh + l * H, t), ld4(p.Rz2h + l * H, t)), ld4(p.b + l * H, t));
    cc[3] = f4add(f4add(ld4(p.zhtil, t), ld4(p.z2h, t)), ld4(p.b + 3 * H, t));

    #pragma unroll
    for (int l = 0; l < 4; ++l) {
        float v = wred(dot4(cc[l], ws));
        if (lane == 0) red2[l][warp] = v;
    }
    __syncthreads();
    if (warp == 0) {
        float v[4];
        #pragma unroll
        for (int l = 0; l < 4; ++l) {
            v[l] = red2[l][lane];
            #pragma unroll
            for (int off = 16; off > 0; off >>= 1)
                v[l] += __shfl_down_sync(0xffffffffu, v[l], off);
        }
        if (lane == 0) {
            int amax = 0; float m1 = v[0];
            for (int l = 1; l < 4; ++l) if (v[l] > m1) { m1 = v[l]; amax = l; }
            float m2 = -INFINITY;
            for (int l = 0; l < 4; ++l) if (l != amax && v[l] > m2) m2 = v[l];
            float e[4], se = 0.f;
            for (int l = 0; l < 4; ++l) { e[l] = __expf(v[l] - m1); se += e[l]; }
            for (int l = 0; l < 4; ++l) wsh[l] = e[l] / se;
            p.out[4096 + 3 + 5] = (float)amax;
            p.out[4096 + 9 + 5] = m1 - m2;
        }
    }
    __syncthreads();

    float4 o = make_float4(0.f, 0.f, 0.f, 0.f);
    #pragma unroll
    for (int l = 0; l < 4; ++l) o = f4smad(wsh[l], cc[l], o);
    ((float4*)p.out)[t] = o;
}

// ---------------------------------------------------------------------------
// Launch sequence (graph-capturable: kernel launches only, default stream).
// ---------------------------------------------------------------------------
extern "C" void kernel_launch(void* const* d_in, const int* in_sizes, int n_in,
                              void* d_out_v, int out_size) {
    float* S = nullptr;
    cudaGetSymbolAddress((void**)&S, g_scratch);

    P p;
    p.L   = (const float*)d_in[2];
    p.R   = (const float*)d_in[3];
    p.x   = (const float*)d_in[0];
    p.hp  = (const float*)d_in[1];
    p.b   = (const float*)d_in[4];
    p.Wsc = (const float*)d_in[5];
    p.out = (float*)d_out_v;

    p.xL     = S + 0 * H;   p.hL     = S + 3 * H;   p.hR     = S + 6 * H;  // hR: 2H
    p.Rr     = S + 8 * H;   p.Rz1    = S + 11 * H;
    p.Rrh    = S + 14 * H;  p.RoneMZ = S + 17 * H;  p.Rz2h   = S + 20 * H;
    p.Lht    = S + 23 * H;  p.Lzh    = S + 26 * H;
    p.r      = S + 29 * H;  p.z1     = S + 30 * H;  p.rh     = S + 31 * H;
    p.oneMZ  = S + 32 * H;  p.z2h    = S + 33 * H;
    p.htilde = S + 34 * H;  p.zhtil  = S + 35 * H;
    p.part   = S + 36 * H;   // <=40K floats of split-tile partials

    const int DSM1 = 1 * H * (int)sizeof(float);   // 16KB
    const int DSM2 = 2 * H * (int)sizeof(float);   // 32KB
    const int DSM3 = 3 * H * (int)sizeof(float);   // 48KB
    cudaFuncSetAttribute(fused_kernel<0>, cudaFuncAttributeMaxDynamicSharedMemorySize, DSM2);
    cudaFuncSetAttribute(fused_kernel<1>, cudaFuncAttributeMaxDynamicSharedMemorySize, DSM2);
    cudaFuncSetAttribute(fused_kernel<2>, cudaFuncAttributeMaxDynamicSharedMemorySize, DSM3);
    cudaFuncSetAttribute(fused_kernel<3>, cudaFuncAttributeMaxDynamicSharedMemorySize, DSM1);
    cudaFuncSetAttribute(fused_kernel<4>, cudaFuncAttributeMaxDynamicSharedMemorySize, DSM1);

    dim3 blk(16, 32);

    fused_kernel<0><<<296, blk, DSM2>>>(p);  // A: L x {x,hp}, R x {hp}      320MB
    fused_kernel<1><<<296, blk, DSM2>>>(p);  // B: glue + R x {r,z1}         192MB
    fused_kernel<2><<<296, blk, DSM3>>>(p);  // C: 3-mix + R x {rh,oMZ,z2h}  192MB
    fused_kernel<3><<<296, blk, DSM1>>>(p);  // D: h_tilde + L x {htilde}    192MB
    fused_kernel<4><<<296, blk, DSM1>>>(p);  // E: zh_tilde + L x {zhtil}    192MB
    final_kernel<<<1, 1024>>>(p);            // F: h_next
}